// round 6
// baseline (speedup 1.0000x reference)
#include <cuda_runtime.h>
#include <cuda_bf16.h>
#include <mma.h>
#include <cstdint>

using namespace nvcuda;

#define NUM 16
#define DIM 128
#define NN (NUM*DIM)            // 2048
#define BATCH 4096
#define INC 512
#define OUTC 512
#define STEPS 10
#define KE 6144                 // 3 segments of 2048 (step chain)
#define KEF 1536                // 3 segments of 512  (final GEMM)
#define KSPLIT 8
#define KC 768                  // per-CTA K for step (KE/KSPLIT)

// ---------------- device scratch ----------------
__device__ __align__(16) __nv_bfloat16 g_Text[NN*KE];        // [Thi|Thi|Tlo], 25MB
__device__ __align__(16) __nv_bfloat16 g_Rt[2][DIM*KE];      // [Rhi|Rlo|Rhi] transposed
__device__ __align__(16) float g_P[KSPLIT*NN*DIM];           // split-K partials, 8MB
__device__ __align__(16) float g_S[NN*DIM];                  // sum R_0..R_9
__device__ __align__(16) float g_Rf[NN*DIM];                 // latest R (fp32)
__device__ __align__(16) __nv_bfloat16 g_Iext[BATCH*KEF];    // [Ihi|Ihi|Ilo], 12.6MB
__device__ __align__(16) __nv_bfloat16 g_Gext[OUTC*KEF];     // rows q: [Ghi|Glo|Ghi] over p
__device__ __align__(16) float g_beta[NN];
__device__ __align__(16) float g_h[DIM];
__device__ __align__(16) float g_WpostT[DIM*OUTC];
__device__ __align__(16) float g_T1[DIM*OUTC];
__device__ __align__(16) float g_G[INC*OUTC];
__device__ __align__(16) float g_dvec[OUTC];

// ---------------- 128x128 GEMM body, 512 threads, 16 warps, BK=32, double-buffered ----------
__device__ __forceinline__ void gemm128(const __nv_bfloat16* __restrict__ Ag,
                                        const __nv_bfloat16* __restrict__ Bg,
                                        long lda, long ldb, int nkc,
                                        float* __restrict__ Out, long ldo) {
    __shared__ __nv_bfloat16 As[2][128][40];
    __shared__ __nv_bfloat16 Bs[2][128][40];
    const int tid = threadIdx.x, wid = tid >> 5;
    const int wm = wid & 3, wn = wid >> 2;          // warp tile rows wm*32, cols wn*32

    wmma::fragment<wmma::accumulator, 16, 16, 16, float> acc[2][2];
#pragma unroll
    for (int r = 0; r < 2; r++)
#pragma unroll
        for (int c = 0; c < 2; c++) wmma::fill_fragment(acc[r][c], 0.0f);

    const int isB = tid >= 256;
    const int lt  = tid & 255;
    const __nv_bfloat16* __restrict__ Gp = isB ? Bg : Ag;
    const long ld = isB ? ldb : lda;
    const int r0  = lt >> 2;                        // 0..63
    const int c8  = (lt & 3) * 8;                   // 0,8,16,24

    // chunk 0 -> buf 0
    uint4 va = *(const uint4*)(Gp + (long)r0*ld + c8);
    uint4 vb = *(const uint4*)(Gp + (long)(64 + r0)*ld + c8);
    {
        __nv_bfloat16* S = isB ? &Bs[0][0][0] : &As[0][0][0];
        *(uint4*)(S + r0*40 + c8)        = va;
        *(uint4*)(S + (64 + r0)*40 + c8) = vb;
    }
    __syncthreads();

    for (int kc = 0; kc < nkc; kc++) {
        const int cb = kc & 1, nb = cb ^ 1;
        if (kc + 1 < nkc) {
            const long kb = (long)(kc + 1) * 32;
            va = *(const uint4*)(Gp + (long)r0*ld + kb + c8);
            vb = *(const uint4*)(Gp + (long)(64 + r0)*ld + kb + c8);
        }
#pragma unroll
        for (int k16 = 0; k16 < 2; k16++) {
            wmma::fragment<wmma::matrix_a, 16, 16, 16, __nv_bfloat16, wmma::row_major> af[2];
            wmma::fragment<wmma::matrix_b, 16, 16, 16, __nv_bfloat16, wmma::col_major> bf[2];
#pragma unroll
            for (int r = 0; r < 2; r++)
                wmma::load_matrix_sync(af[r], &As[cb][wm*32 + r*16][k16*16], 40);
#pragma unroll
            for (int c = 0; c < 2; c++)
                wmma::load_matrix_sync(bf[c], &Bs[cb][wn*32 + c*16][k16*16], 40);
#pragma unroll
            for (int r = 0; r < 2; r++)
#pragma unroll
                for (int c = 0; c < 2; c++)
                    wmma::mma_sync(acc[r][c], af[r], bf[c], acc[r][c]);
        }
        if (kc + 1 < nkc) {
            __nv_bfloat16* S = isB ? &Bs[nb][0][0] : &As[nb][0][0];
            *(uint4*)(S + r0*40 + c8)        = va;
            *(uint4*)(S + (64 + r0)*40 + c8) = vb;
        }
        __syncthreads();
    }
#pragma unroll
    for (int r = 0; r < 2; r++)
#pragma unroll
        for (int c = 0; c < 2; c++)
            wmma::store_matrix_sync(Out + (long)(wm*32 + r*16)*ldo + wn*32 + c*16,
                                    acc[r][c], ldo, wmma::mem_row_major);
}

// step MMA: partial[ks] = T_ext[mtile, ksK] @ Rt[cur][:, ksK]^T   (cur passed as int — FIX)
__global__ void __launch_bounds__(512, 1) k_mma_step(int cur) {
    const int ks = blockIdx.x, mt = blockIdx.y;
    gemm128(g_Text + (size_t)mt*128*KE + ks*KC, g_Rt[cur] + ks*KC,
            KE, KE, KC/32,
            g_P + ((size_t)ks*NN + mt*128)*DIM, DIM);
}

// final MMA: out = I_ext @ G_ext^T
__global__ void __launch_bounds__(512, 1) k_mma_fin(float* __restrict__ out) {
    const int qt = blockIdx.x, bt = blockIdx.y;
    gemm128(g_Iext + (size_t)bt*128*KEF, g_Gext + (size_t)qt*128*KEF,
            KEF, KEF, KEF/32,
            out + (size_t)bt*128*OUTC + qt*128, OUTC);
}

// out[b][q] += dvec[q]
__global__ void k_bias(float* __restrict__ out) {
    int idx = blockIdx.x*256 + threadIdx.x;
    int q4 = idx & (OUTC/4 - 1);
    float4 v = *(float4*)&out[idx*4];
    float4 d = *(const float4*)&g_dvec[q4*4];
    v.x += d.x; v.y += d.y; v.z += d.z; v.w += d.w;
    *(float4*)&out[idx*4] = v;
}

// ---------------- prep kernels ----------------

__global__ void k_prep(const float* __restrict__ life, const float* __restrict__ bl) {
    int j = blockIdx.x, g = threadIdx.x;
    float s = 0.f;
#pragma unroll
    for (int i = 0; i < NUM; i++) {
        float gt = fmaxf(life[i*NUM + j], 0.f);
        s += gt * bl[(i*NUM + j)*DIM + g];
    }
    g_beta[j*DIM + g] = s;
}

__global__ void k_transpose(const float* __restrict__ Wpost) {
    int e = blockIdx.x, q = threadIdx.x;
    g_WpostT[e*OUTC + q] = Wpost[q*DIM + e];
}

// T_ext[(i,f)][(j,g)] split of gate[i,j]*W[i,j,g,f]; segments [Thi|Thi|Tlo], bf16x2 stores
__global__ void k_make_T(const float* __restrict__ W, const float* __restrict__ life) {
    const int j = blockIdx.x, i = blockIdx.y;
    const float gate = fmaxf(life[i*NUM + j], 0.f);
    const float* __restrict__ Wb = W + (size_t)(i*NUM + j)*DIM*DIM;   // [g][f]
    __shared__ float sm[32][DIM + 1];
    const int tid = threadIdx.x;
    for (int g0 = 0; g0 < DIM; g0 += 32) {
        for (int u = tid; u < 32*DIM; u += 256) {
            int gg = u >> 7, f = u & 127;
            sm[gg][f] = Wb[(size_t)(g0 + gg)*DIM + f];
        }
        __syncthreads();
#pragma unroll
        for (int it = 0; it < 8; it++) {
            int pi = it*256 + tid;
            int f = pi >> 4, gp = (pi & 15) * 2;
            float x0 = gate * sm[gp][f];
            float x1 = gate * sm[gp + 1][f];
            __nv_bfloat16 h0 = __float2bfloat16(x0);
            __nv_bfloat16 h1 = __float2bfloat16(x1);
            __nv_bfloat162 hv; hv.x = h0; hv.y = h1;
            __nv_bfloat162 lv;
            lv.x = __float2bfloat16(x0 - __bfloat162float(h0));
            lv.y = __float2bfloat16(x1 - __bfloat162float(h1));
            size_t row = (size_t)(i*DIM + f)*KE;
            int col = j*DIM + g0 + gp;
            *(__nv_bfloat162*)&g_Text[row + col]        = hv;
            *(__nv_bfloat162*)&g_Text[row + 2048 + col] = hv;
            *(__nv_bfloat162*)&g_Text[row + 4096 + col] = lv;
        }
        __syncthreads();
    }
}

// Rt[0] rows r (<128): [Rhi|Rlo|Rhi] of identity block-15 columns; S = R_0 (fp32)
__global__ void k_initRS() {
    int r = blockIdx.x, e = threadIdx.x;     // grid 2048 x 128
    g_S[(size_t)r*DIM + e] = (r == (NN - DIM) + e) ? 1.f : 0.f;
    if (r < DIM) {
#pragma unroll
        for (int it = 0; it < 24; it++) {
            int cp = (it*128 + e) * 2;
            int seg = cp >> 11, cc = cp & 2047;
            float v0 = ((seg == 0 || seg == 2) && cc     == (NN - DIM) + r) ? 1.f : 0.f;
            float v1 = ((seg == 0 || seg == 2) && cc + 1 == (NN - DIM) + r) ? 1.f : 0.f;
            __nv_bfloat162 v; v.x = __float2bfloat16(v0); v.y = __float2bfloat16(v1);
            *(__nv_bfloat162*)&g_Rt[0][(size_t)r*KE + cp] = v;
        }
    }
}

// reduce split-K partials -> Rf (fp32), S accum, re-split transposed into Rt[cur^1]
__global__ void k_reduce2(int cur, int addS) {
    const int mt = blockIdx.x, sl = blockIdx.y;
    const int base_r = mt*128 + sl*32;
    __shared__ float slab[32][DIM + 1];
    const int tid = threadIdx.x;
    for (int u = tid; u < 32*DIM; u += 256) {
        int rr = u >> 7, e = u & 127;
        float v = 0.f;
#pragma unroll
        for (int k = 0; k < KSPLIT; k++)
            v += g_P[(size_t)k*NN*DIM + (size_t)(base_r + rr)*DIM + e];
        g_Rf[(size_t)(base_r + rr)*DIM + e] = v;
        if (addS) g_S[(size_t)(base_r + rr)*DIM + e] += v;
        slab[rr][e] = v;
    }
    __syncthreads();
    int e = tid >> 1, hh = tid & 1;
    __nv_bfloat16* Rt = g_Rt[cur ^ 1];
#pragma unroll
    for (int k = 0; k < 16; k++) {
        int rr = hh*16 + k;
        float v = slab[rr][e];
        __nv_bfloat16 h = __float2bfloat16(v);
        __nv_bfloat16 l = __float2bfloat16(v - __bfloat162float(h));
        int col = base_r + rr;
        Rt[(size_t)e*KE + col]        = h;   // seg0: Rhi (pairs Thi)
        Rt[(size_t)e*KE + 2048 + col] = l;   // seg1: Rlo (pairs Thi)
        Rt[(size_t)e*KE + 4096 + col] = h;   // seg2: Rhi (pairs Tlo)
    }
}

// ---------------- combine kernels ----------------
__global__ void k_h(const float* __restrict__ bpre) {
    int e = blockIdx.x, tid = threadIdx.x;
    float s = 0.f;
    for (int r = tid; r < NN; r += 256) s += g_beta[r] * g_S[(size_t)r*DIM + e];
    if (tid < DIM) s += bpre[tid] * g_Rf[(size_t)tid*DIM + e];
    __shared__ float red[256];
    red[tid] = s;
    __syncthreads();
    for (int off = 128; off > 0; off >>= 1) {
        if (tid < off) red[tid] += red[tid + off];
        __syncthreads();
    }
    if (tid == 0) g_h[e] = red[0];
}

__global__ void k_T1() {
    int d = blockIdx.y;
    int q = blockIdx.x*128 + threadIdx.x;
    const float* __restrict__ Er = g_Rf + (size_t)d*DIM;
    float acc = 0.f;
#pragma unroll 8
    for (int e = 0; e < DIM; e++) acc += Er[e] * g_WpostT[e*OUTC + q];
    g_T1[d*OUTC + q] = acc;
}

__global__ void k_G(const float* __restrict__ Wpre) {
    int p = blockIdx.y;
    int q = blockIdx.x*128 + threadIdx.x;
    float acc = 0.f;
#pragma unroll 8
    for (int d = 0; d < DIM; d++) acc += Wpre[d*INC + p] * g_T1[d*OUTC + q];
    g_G[p*OUTC + q] = acc;
}

__global__ void k_dvec(const float* __restrict__ bpost) {
    int q = blockIdx.x*128 + threadIdx.x;
    float acc = bpost[q];
#pragma unroll 8
    for (int e = 0; e < DIM; e++) acc += g_h[e] * g_WpostT[e*OUTC + q];
    g_dvec[q] = acc;
}

// inp -> [Ihi|Ihi|Ilo], bf16x2 coalesced
__global__ void k_split_inp(const float* __restrict__ inp) {
    int b = blockIdx.x, tid = threadIdx.x;
#pragma unroll
    for (int it = 0; it < 2; it++) {
        int qp = (it*128 + tid) * 2;
        float2 x = *(const float2*)&inp[(size_t)b*INC + qp];
        __nv_bfloat16 h0 = __float2bfloat16(x.x);
        __nv_bfloat16 h1 = __float2bfloat16(x.y);
        __nv_bfloat162 hv; hv.x = h0; hv.y = h1;
        __nv_bfloat162 lv;
        lv.x = __float2bfloat16(x.x - __bfloat162float(h0));
        lv.y = __float2bfloat16(x.y - __bfloat162float(h1));
        size_t ro = (size_t)b*KEF;
        *(__nv_bfloat162*)&g_Iext[ro + qp]        = hv;
        *(__nv_bfloat162*)&g_Iext[ro + 512 + qp]  = hv;
        *(__nv_bfloat162*)&g_Iext[ro + 1024 + qp] = lv;
    }
}
// Gext row q over p: [hi(G[p][q]) | lo(G[p][q]) | hi(G[p][q])]
__global__ void k_split_G() {
    int q = blockIdx.x;
    for (int p = threadIdx.x; p < INC; p += 128) {
        float x = g_G[(size_t)p*OUTC + q];
        __nv_bfloat16 h = __float2bfloat16(x);
        __nv_bfloat16 l = __float2bfloat16(x - __bfloat162float(h));
        size_t ro = (size_t)q*KEF;
        g_Gext[ro + p]        = h;
        g_Gext[ro + 512 + p]  = l;
        g_Gext[ro + 1024 + p] = h;
    }
}

// ---------------- launch ----------------
extern "C" void kernel_launch(void* const* d_in, const int* in_sizes, int n_in,
                              void* d_out, int out_size) {
    (void)in_sizes; (void)n_in; (void)out_size;
    const float* inp   = (const float*)d_in[0];
    const float* Wpre  = (const float*)d_in[1];
    const float* bpre  = (const float*)d_in[2];
    const float* W     = (const float*)d_in[3];
    const float* bl    = (const float*)d_in[4];
    const float* life  = (const float*)d_in[5];
    const float* Wpost = (const float*)d_in[6];
    const float* bpost = (const float*)d_in[7];
    float* out = (float*)d_out;

    k_prep<<<NUM, DIM>>>(life, bl);                 // launch 0
    k_transpose<<<DIM, OUTC>>>(Wpost);              // 1
    k_make_T<<<dim3(NUM, NUM), 256>>>(W, life);     // 2
    k_initRS<<<NN, DIM>>>();                        // 3
    k_split_inp<<<BATCH, 128>>>(inp);               // 4

    int cur = 0;
    for (int s = 0; s < STEPS; s++) {
        k_mma_step<<<dim3(KSPLIT, NUM), 512>>>(cur);   // first one = launch 5 (ncu -s 5)
        k_reduce2<<<dim3(NUM, 4), 256>>>(cur, (s < STEPS - 1) ? 1 : 0);
        cur ^= 1;
    }

    k_h<<<DIM, 256>>>(bpre);
    k_T1<<<dim3(OUTC/128, DIM), 128>>>();
    k_G<<<dim3(OUTC/128, INC), 128>>>(Wpre);
    k_dvec<<<OUTC/128, 128>>>(bpost);
    k_split_G<<<OUTC, 128>>>();
    k_mma_fin<<<dim3(OUTC/128, BATCH/128), 512>>>(out);
    k_bias<<<BATCH*OUTC/1024, 256>>>(out);
}